// round 1
// baseline (speedup 1.0000x reference)
#include <cuda_runtime.h>
#include <cuda_bf16.h>

#define EPSF 1e-8f
#define LNK 16
#define DST 255
#define TUN 1020
#define WARPS 8

// Scratch for deterministic two-pass reduction (no cudaMalloc allowed).
__device__ float g_partials[4096];

__global__ __launch_bounds__(256) void loss_main_kernel(
    const float* __restrict__ pred,   // [B, 1020]
    const float* __restrict__ dem,    // [B, 255]
    const float* __restrict__ clu,    // [B, 16]
    const float* __restrict__ caps,   // [16]
    const int*   __restrict__ t2l,    // [1020]
    int B)
{
    __shared__ int   s_t2l[TUN];
    __shared__ float s_inv[LNK];
    __shared__ float s_red[WARPS][32 * 17];
    __shared__ float s_loss[WARPS];

    const int tid = threadIdx.x;

    // Stage constant data
    for (int i = tid; i < TUN; i += 256) s_t2l[i] = t2l[i];
    if (tid < LNK) s_inv[tid] = 1.0f / (caps[tid] + EPSF);
    __syncthreads();

    const int warp = tid >> 5;
    const int lane = tid & 31;
    const int b = blockIdx.x * WARPS + warp;

    float loss = 0.0f;
    if (b < B) {
        const float4* __restrict__ pr = (const float4*)(pred + (size_t)b * TUN);
        const float*  __restrict__ dr = dem + (size_t)b * DST;
        const int4*   lt = (const int4*)s_t2l;

        float acc[16];
        #pragma unroll
        for (int j = 0; j < 16; ++j) acc[j] = 0.0f;

        // 255 float4 groups per row; group index == destination index (K=4).
        #pragma unroll
        for (int it = 0; it < 8; ++it) {
            const int idx = lane + it * 32;
            if (idx < DST) {
                const float4 r  = pr[idx];
                const float  d  = dr[idx];
                const int4   l4 = lt[idx];
                // Scatter: 16 predicated FFMAs per slot (warp-wide, no local mem).
                #pragma unroll
                for (int j = 0; j < 16; ++j) {
                    if (l4.x == j) acc[j] = fmaf(r.x, d, acc[j]);
                    if (l4.y == j) acc[j] = fmaf(r.y, d, acc[j]);
                    if (l4.z == j) acc[j] = fmaf(r.z, d, acc[j]);
                    if (l4.w == j) acc[j] = fmaf(r.w, d, acc[j]);
                }
            }
        }

        // Cross-lane bin reduction via padded shared transpose (stride 17 => conflict-free).
        float* myrow = &s_red[warp][lane * 17];
        #pragma unroll
        for (int j = 0; j < 16; ++j) myrow[j] = acc[j];
        __syncwarp();

        const int j = lane & 15;   // lanes 16..31 duplicate lanes 0..15 (broadcast reads)
        float b0 = 0.f, b1 = 0.f, b2 = 0.f, b3 = 0.f;
        #pragma unroll
        for (int i = 0; i < 32; i += 4) {
            b0 += s_red[warp][(i + 0) * 17 + j];
            b1 += s_red[warp][(i + 1) * 17 + j];
            b2 += s_red[warp][(i + 2) * 17 + j];
            b3 += s_red[warp][(i + 3) * 17 + j];
        }
        const float bin = (b0 + b1) + (b2 + b3);

        const float u   = bin * s_inv[j];
        const float cur = clu[(size_t)b * LNK + j];

        // 16-lane group reductions (xor offsets 1,2,4,8 stay within each half).
        float s = u;
        #pragma unroll
        for (int off = 1; off < 16; off <<= 1)
            s += __shfl_xor_sync(0xffffffffu, s, off);
        const float mean = s * (1.0f / 16.0f);

        const float dvt = u - mean;
        float q   = dvt * dvt;
        float dot = u * cur;
        float mx  = u;
        #pragma unroll
        for (int off = 1; off < 16; off <<= 1) {
            q   += __shfl_xor_sync(0xffffffffu, q, off);
            dot += __shfl_xor_sync(0xffffffffu, dot, off);
            mx   = fmaxf(mx, __shfl_xor_sync(0xffffffffu, mx, off));
        }
        const float var = q * (1.0f / 15.0f);  // ddof=1
        loss = 0.3f * var + 0.5f * dot + 0.2f * mx;
    }

    if (lane == 0) s_loss[warp] = loss;
    __syncthreads();
    if (tid == 0) {
        float t = 0.0f;
        #pragma unroll
        for (int w = 0; w < WARPS; ++w) t += s_loss[w];
        g_partials[blockIdx.x] = t;
    }
}

__global__ __launch_bounds__(1024) void loss_reduce_kernel(float* __restrict__ out,
                                                           int nb, float invB)
{
    __shared__ float sh[1024];
    const int tid = threadIdx.x;
    float v = 0.0f;
    for (int i = tid; i < nb; i += 1024) v += g_partials[i];
    sh[tid] = v;
    __syncthreads();
    #pragma unroll
    for (int s = 512; s > 0; s >>= 1) {
        if (tid < s) sh[tid] += sh[tid + s];
        __syncthreads();
    }
    if (tid == 0) out[0] = sh[0] * invB;
}

extern "C" void kernel_launch(void* const* d_in, const int* in_sizes, int n_in,
                              void* d_out, int out_size)
{
    const float* pred = (const float*)d_in[0];  // pred_ratios [B,1020]
    const float* dem  = (const float*)d_in[1];  // demands     [B,255]
    const float* clu  = (const float*)d_in[2];  // current_link_utils [B,16]
    const float* caps = (const float*)d_in[3];  // link_capacities [16]
    const int*   t2l  = (const int*)d_in[4];    // tunnel_to_link [1020]
    float* out = (float*)d_out;

    const int B  = in_sizes[0] / TUN;           // 16384
    const int nb = (B + WARPS - 1) / WARPS;     // 2048 blocks

    loss_main_kernel<<<nb, 256>>>(pred, dem, clu, caps, t2l, B);
    loss_reduce_kernel<<<1, 1024>>>(out, nb, 1.0f / (float)B);
}